// round 2
// baseline (speedup 1.0000x reference)
#include <cuda_runtime.h>

// Problem constants
#define NVEC 65536      // 64*32*32 vectors
#define DIM  256        // embedding dim
#define KCB  4096       // codebook entries

// GEMM tiling
#define BN 128          // rows per CTA
#define BK 128          // codes per k-tile
#define DC 16           // d-chunk depth
#define TM 8            // rows per thread (4 packed pairs)
#define TK 8            // codes per thread
// 256 threads = 16x16 (tx: codes, ty: rows)

#define ES_PITCH 514    // floats per d-row of duplicated e-tile (256 dup + 2 pad)

#define LOSS_BLOCKS 1184

__device__ float  g_x2[NVEC];
__device__ float  g_e2[KCB];
__device__ int    g_idx[NVEC];
__device__ double g_part[LOSS_BLOCKS];

__device__ __forceinline__ unsigned fenc(float f) {
    unsigned u = __float_as_uint(f);
    return (u & 0x80000000u) ? ~u : (u | 0x80000000u);
}

// ---------------------------------------------------------------------------
// Row squared-norms: one warp per row, tree reduction.
// ---------------------------------------------------------------------------
__global__ void rownorm_kernel(const float* __restrict__ v, int rows, int which) {
    int row  = blockIdx.x * (blockDim.x >> 5) + (threadIdx.x >> 5);
    int lane = threadIdx.x & 31;
    if (row >= rows) return;
    const float4* p = reinterpret_cast<const float4*>(v + (size_t)row * DIM);
    float4 a = p[lane];
    float4 b = p[lane + 32];
    float s = ((a.x * a.x + a.y * a.y) + (a.z * a.z + a.w * a.w))
            + ((b.x * b.x + b.y * b.y) + (b.z * b.z + b.w * b.w));
    #pragma unroll
    for (int off = 16; off; off >>= 1)
        s += __shfl_xor_sync(0xffffffffu, s, off);
    if (lane == 0) {
        if (which) g_e2[row] = s;
        else       g_x2[row] = s;
    }
}

// ---------------------------------------------------------------------------
// Fused distance-GEMM + argmin using packed fma.rn.f32x2 (FFMA2).
// Packing is along ROWS (x side); codebook values are duplicated in smem so
// each accumulator lane is a plain sequential fp32 fma chain over d —
// bit-identical numerics to the scalar version.
// ---------------------------------------------------------------------------
__global__ __launch_bounds__(256, 2)
void vq_argmin_kernel(const float* __restrict__ x, const float* __restrict__ cb) {
    // xs: d-major, 4-row groups XOR-swizzled by d: phys(d,r)=d*128+((r>>2)^d)*4+(r&3)
    __shared__ float xs[DC * BN];
    // es: duplicated codebook tile: es[d*ES_PITCH + 2k] = es[.. +2k+1] = e[k][d]
    __shared__ float es[DC * ES_PITCH];
    __shared__ unsigned long long red[BN];

    const int tid = threadIdx.x;
    const int tx  = tid & 15;
    const int ty  = tid >> 4;
    const int row0 = blockIdx.x * BN;

    float bestv[TM];
    int   besti[TM];
    #pragma unroll
    for (int i = 0; i < TM; i++) { bestv[i] = 3.4e38f; besti[i] = 0; }

    const int ld_d = tid & 15;    // d within chunk (0..15)
    const int ld_r = tid >> 4;    // base row (0..15)

    const float* xbase = x + (size_t)row0 * DIM;

    for (int kt = 0; kt < KCB; kt += BK) {
        unsigned long long acc[4][TK];
        #pragma unroll
        for (int p = 0; p < 4; p++)
            #pragma unroll
            for (int j = 0; j < TK; j++) acc[p][j] = 0ull;

        const float* cbase = cb + (size_t)kt * DIM;

        for (int d0 = 0; d0 < DIM; d0 += DC) {
            __syncthreads();
            // Fill x tile (swizzled) and duplicated e tile.
            #pragma unroll
            for (int i = 0; i < 8; i++) {
                int r = ld_r + i * 16;
                float vx = xbase[(size_t)r * DIM + d0 + ld_d];
                float ve = cbase[(size_t)r * DIM + d0 + ld_d];
                int c = ((r >> 2) ^ ld_d);
                xs[ld_d * 128 + (c << 2) + (r & 3)] = vx;
                unsigned ue = __float_as_uint(ve);
                unsigned long long pv = (unsigned long long)ue | ((unsigned long long)ue << 32);
                *reinterpret_cast<unsigned long long*>(&es[ld_d * ES_PITCH + (r << 1)]) = pv;
            }
            __syncthreads();

            #pragma unroll 4
            for (int d = 0; d < DC; d++) {
                ulonglong2 A0 = *reinterpret_cast<const ulonglong2*>(
                    &xs[d * 128 + ((((ty << 1)    ) ^ d) << 2)]);
                ulonglong2 A1 = *reinterpret_cast<const ulonglong2*>(
                    &xs[d * 128 + ((((ty << 1) + 1) ^ d) << 2)]);
                unsigned long long Ap[4] = {A0.x, A0.y, A1.x, A1.y};
                unsigned long long Bp[TK];
                #pragma unroll
                for (int j = 0; j < TK; j++)
                    Bp[j] = *reinterpret_cast<const unsigned long long*>(
                        &es[d * ES_PITCH + ((j * 16 + tx) << 1)]);
                #pragma unroll
                for (int p = 0; p < 4; p++)
                    #pragma unroll
                    for (int j = 0; j < TK; j++)
                        asm("fma.rn.f32x2 %0, %1, %2, %0;"
                            : "+l"(acc[p][j]) : "l"(Ap[p]), "l"(Bp[j]));
            }
        }

        // Epilogue: fp32-quantized distance, running argmin (strict < keeps lowest k)
        #pragma unroll
        for (int p = 0; p < 4; p++) {
            int r_lo = ty * TM + 2 * p;
            float x2lo = g_x2[row0 + r_lo];
            float x2hi = g_x2[row0 + r_lo + 1];
            #pragma unroll
            for (int j = 0; j < TK; j++) {
                int k = kt + j * 16 + tx;
                float e2 = g_e2[k];
                float dlo = __uint_as_float((unsigned)(acc[p][j] & 0xffffffffull));
                float dhi = __uint_as_float((unsigned)(acc[p][j] >> 32));
                float distlo = (x2lo + e2) - 2.0f * dlo;
                float disthi = (x2hi + e2) - 2.0f * dhi;
                if (distlo < bestv[2 * p])     { bestv[2 * p]     = distlo; besti[2 * p]     = k; }
                if (disthi < bestv[2 * p + 1]) { bestv[2 * p + 1] = disthi; besti[2 * p + 1] = k; }
            }
        }
    }

    // Cross-thread argmin: 64-bit key = (ordered float, idx); min => lowest idx on tie
    if (tid < BN) red[tid] = 0xFFFFFFFFFFFFFFFFull;
    __syncthreads();
    #pragma unroll
    for (int i = 0; i < TM; i++) {
        int r = ty * TM + i;
        unsigned long long key =
            ((unsigned long long)fenc(bestv[i]) << 32) | (unsigned)besti[i];
        atomicMin(&red[r], key);
    }
    __syncthreads();
    if (tid < BN) g_idx[row0 + tid] = (int)(red[tid] & 0xFFFFFFFFu);
}

// ---------------------------------------------------------------------------
// Gather + straight-through output + per-block loss partials (double accum).
// ---------------------------------------------------------------------------
__global__ void vq_output_kernel(const float* __restrict__ x,
                                 const float* __restrict__ cb,
                                 float* __restrict__ out) {
    __shared__ double sred[256];
    double lsum = 0.0;
    const int nthreads = gridDim.x * blockDim.x;
    const int total4 = NVEC * DIM / 4;
    const float4* x4 = reinterpret_cast<const float4*>(x);
    float4* o4 = reinterpret_cast<float4*>(out);

    for (int i = blockIdx.x * blockDim.x + threadIdx.x; i < total4; i += nthreads) {
        int n = i >> 6;                 // 64 float4 per row
        int idx = g_idx[n];
        float4 q  = reinterpret_cast<const float4*>(cb + (size_t)idx * DIM)[i & 63];
        float4 xv = x4[i];
        float4 r;
        float d0 = q.x - xv.x; r.x = xv.x + d0; lsum += (double)(d0 * d0);
        float d1 = q.y - xv.y; r.y = xv.y + d1; lsum += (double)(d1 * d1);
        float d2 = q.z - xv.z; r.z = xv.z + d2; lsum += (double)(d2 * d2);
        float d3 = q.w - xv.w; r.w = xv.w + d3; lsum += (double)(d3 * d3);
        o4[i] = r;
    }
    sred[threadIdx.x] = lsum;
    __syncthreads();
    #pragma unroll
    for (int s = 128; s; s >>= 1) {
        if (threadIdx.x < s) sred[threadIdx.x] += sred[threadIdx.x + s];
        __syncthreads();
    }
    if (threadIdx.x == 0) g_part[blockIdx.x] = sred[0];
}

// ---------------------------------------------------------------------------
// Final loss reduction + tail fill
// ---------------------------------------------------------------------------
__global__ void loss_kernel(float* __restrict__ out, int out_size) {
    __shared__ double sred[256];
    double s = 0.0;
    for (int i = threadIdx.x; i < LOSS_BLOCKS; i += 256) s += g_part[i];
    sred[threadIdx.x] = s;
    __syncthreads();
    #pragma unroll
    for (int k = 128; k; k >>= 1) {
        if (threadIdx.x < k) sred[threadIdx.x] += sred[threadIdx.x + k];
        __syncthreads();
    }
    const int nq = NVEC * DIM;
    if (threadIdx.x == 0) {
        double m = sred[0] / (double)nq;
        float mf = (float)m;
        float loss = mf + 0.25f * mf;
        if (out_size == nq + 1)      out[nq] = loss;
        else if (out_size == 1)      out[0] = loss;
        else if (out_size > nq)      out[out_size - 1] = loss;
    }
    for (int i = nq + 1 + threadIdx.x; i < out_size - 1; i += 256) out[i] = 0.f;
}

// ---------------------------------------------------------------------------
extern "C" void kernel_launch(void* const* d_in, const int* in_sizes, int n_in,
                              void* d_out, int out_size) {
    const float* x  = (const float*)d_in[0];
    const float* cb = (const float*)d_in[1];
    if (n_in >= 2 && in_sizes[0] == KCB * DIM && in_sizes[1] == NVEC * DIM) {
        const float* t = x; x = cb; cb = t;
    }
    float* out = (float*)d_out;

    rownorm_kernel<<<NVEC / 8, 256>>>(x,  NVEC, 0);
    rownorm_kernel<<<KCB  / 8, 256>>>(cb, KCB,  1);
    vq_argmin_kernel<<<NVEC / BN, 256>>>(x, cb);
    vq_output_kernel<<<LOSS_BLOCKS, 256>>>(x, cb, out);
    loss_kernel<<<1, 256>>>(out, out_size);
}

// round 3
// speedup vs baseline: 1.0009x; 1.0009x over previous
#include <cuda_runtime.h>

// Problem constants
#define NVEC 65536      // 64*32*32 vectors
#define DIM  256        // embedding dim
#define KCB  4096       // codebook entries

// GEMM tiling
#define BN 128          // rows per CTA
#define BK 128          // codes per k-tile
#define DC 16           // d-chunk depth
#define TM 8            // rows per thread (4 packed pairs)
#define TK 8            // codes per thread
// 256 threads = 16x16 (tx: codes, ty: rows)

#define ES_PITCH 514    // floats per d-row of duplicated e-tile (256 dup + 2 pad)

#define LOSS_BLOCKS 1184

__device__ float  g_x2[NVEC];
__device__ float  g_e2[KCB];
__device__ int    g_idx[NVEC];
__device__ double g_part[LOSS_BLOCKS];

__device__ __forceinline__ unsigned fenc(float f) {
    unsigned u = __float_as_uint(f);
    return (u & 0x80000000u) ? ~u : (u | 0x80000000u);
}

// ---------------------------------------------------------------------------
// Row squared-norms: one warp per row, tree reduction.
// ---------------------------------------------------------------------------
__global__ void rownorm_kernel(const float* __restrict__ v, int rows, int which) {
    int row  = blockIdx.x * (blockDim.x >> 5) + (threadIdx.x >> 5);
    int lane = threadIdx.x & 31;
    if (row >= rows) return;
    const float4* p = reinterpret_cast<const float4*>(v + (size_t)row * DIM);
    float4 a = p[lane];
    float4 b = p[lane + 32];
    float s = ((a.x * a.x + a.y * a.y) + (a.z * a.z + a.w * a.w))
            + ((b.x * b.x + b.y * b.y) + (b.z * b.z + b.w * b.w));
    #pragma unroll
    for (int off = 16; off; off >>= 1)
        s += __shfl_xor_sync(0xffffffffu, s, off);
    if (lane == 0) {
        if (which) g_e2[row] = s;
        else       g_x2[row] = s;
    }
}

// ---------------------------------------------------------------------------
// Fused distance-GEMM + argmin using packed fma.rn.f32x2 (FFMA2).
// Packing is along ROWS (x side); codebook values are duplicated in smem so
// each accumulator lane is a plain sequential fp32 fma chain over d —
// bit-identical numerics to the scalar version.
// ---------------------------------------------------------------------------
__global__ __launch_bounds__(256, 2)
void vq_argmin_kernel(const float* __restrict__ x, const float* __restrict__ cb) {
    // xs: d-major, 4-row groups XOR-swizzled by d: phys(d,r)=d*128+((r>>2)^d)*4+(r&3)
    __shared__ float xs[DC * BN];
    // es: duplicated codebook tile: es[d*ES_PITCH + 2k] = es[.. +2k+1] = e[k][d]
    __shared__ float es[DC * ES_PITCH];
    __shared__ unsigned long long red[BN];

    const int tid = threadIdx.x;
    const int tx  = tid & 15;
    const int ty  = tid >> 4;
    const int row0 = blockIdx.x * BN;

    float bestv[TM];
    int   besti[TM];
    #pragma unroll
    for (int i = 0; i < TM; i++) { bestv[i] = 3.4e38f; besti[i] = 0; }

    const int ld_d = tid & 15;    // d within chunk (0..15)
    const int ld_r = tid >> 4;    // base row (0..15)

    const float* xbase = x + (size_t)row0 * DIM;

    for (int kt = 0; kt < KCB; kt += BK) {
        unsigned long long acc[4][TK];
        #pragma unroll
        for (int p = 0; p < 4; p++)
            #pragma unroll
            for (int j = 0; j < TK; j++) acc[p][j] = 0ull;

        const float* cbase = cb + (size_t)kt * DIM;

        for (int d0 = 0; d0 < DIM; d0 += DC) {
            __syncthreads();
            // Fill x tile (swizzled) and duplicated e tile.
            #pragma unroll
            for (int i = 0; i < 8; i++) {
                int r = ld_r + i * 16;
                float vx = xbase[(size_t)r * DIM + d0 + ld_d];
                float ve = cbase[(size_t)r * DIM + d0 + ld_d];
                int c = ((r >> 2) ^ ld_d);
                xs[ld_d * 128 + (c << 2) + (r & 3)] = vx;
                unsigned ue = __float_as_uint(ve);
                unsigned long long pv = (unsigned long long)ue | ((unsigned long long)ue << 32);
                *reinterpret_cast<unsigned long long*>(&es[ld_d * ES_PITCH + (r << 1)]) = pv;
            }
            __syncthreads();

            #pragma unroll 4
            for (int d = 0; d < DC; d++) {
                ulonglong2 A0 = *reinterpret_cast<const ulonglong2*>(
                    &xs[d * 128 + ((((ty << 1)    ) ^ d) << 2)]);
                ulonglong2 A1 = *reinterpret_cast<const ulonglong2*>(
                    &xs[d * 128 + ((((ty << 1) + 1) ^ d) << 2)]);
                unsigned long long Ap[4] = {A0.x, A0.y, A1.x, A1.y};
                unsigned long long Bp[TK];
                #pragma unroll
                for (int j = 0; j < TK; j++)
                    Bp[j] = *reinterpret_cast<const unsigned long long*>(
                        &es[d * ES_PITCH + ((j * 16 + tx) << 1)]);
                #pragma unroll
                for (int p = 0; p < 4; p++)
                    #pragma unroll
                    for (int j = 0; j < TK; j++)
                        asm("fma.rn.f32x2 %0, %1, %2, %0;"
                            : "+l"(acc[p][j]) : "l"(Ap[p]), "l"(Bp[j]));
            }
        }

        // Epilogue: fp32-quantized distance, running argmin (strict < keeps lowest k)
        #pragma unroll
        for (int p = 0; p < 4; p++) {
            int r_lo = ty * TM + 2 * p;
            float x2lo = g_x2[row0 + r_lo];
            float x2hi = g_x2[row0 + r_lo + 1];
            #pragma unroll
            for (int j = 0; j < TK; j++) {
                int k = kt + j * 16 + tx;
                float e2 = g_e2[k];
                float dlo = __uint_as_float((unsigned)(acc[p][j] & 0xffffffffull));
                float dhi = __uint_as_float((unsigned)(acc[p][j] >> 32));
                float distlo = (x2lo + e2) - 2.0f * dlo;
                float disthi = (x2hi + e2) - 2.0f * dhi;
                if (distlo < bestv[2 * p])     { bestv[2 * p]     = distlo; besti[2 * p]     = k; }
                if (disthi < bestv[2 * p + 1]) { bestv[2 * p + 1] = disthi; besti[2 * p + 1] = k; }
            }
        }
    }

    // Cross-thread argmin: 64-bit key = (ordered float, idx); min => lowest idx on tie
    if (tid < BN) red[tid] = 0xFFFFFFFFFFFFFFFFull;
    __syncthreads();
    #pragma unroll
    for (int i = 0; i < TM; i++) {
        int r = ty * TM + i;
        unsigned long long key =
            ((unsigned long long)fenc(bestv[i]) << 32) | (unsigned)besti[i];
        atomicMin(&red[r], key);
    }
    __syncthreads();
    if (tid < BN) g_idx[row0 + tid] = (int)(red[tid] & 0xFFFFFFFFu);
}

// ---------------------------------------------------------------------------
// Gather + straight-through output + per-block loss partials (double accum).
// ---------------------------------------------------------------------------
__global__ void vq_output_kernel(const float* __restrict__ x,
                                 const float* __restrict__ cb,
                                 float* __restrict__ out) {
    __shared__ double sred[256];
    double lsum = 0.0;
    const int nthreads = gridDim.x * blockDim.x;
    const int total4 = NVEC * DIM / 4;
    const float4* x4 = reinterpret_cast<const float4*>(x);
    float4* o4 = reinterpret_cast<float4*>(out);

    for (int i = blockIdx.x * blockDim.x + threadIdx.x; i < total4; i += nthreads) {
        int n = i >> 6;                 // 64 float4 per row
        int idx = g_idx[n];
        float4 q  = reinterpret_cast<const float4*>(cb + (size_t)idx * DIM)[i & 63];
        float4 xv = x4[i];
        float4 r;
        float d0 = q.x - xv.x; r.x = xv.x + d0; lsum += (double)(d0 * d0);
        float d1 = q.y - xv.y; r.y = xv.y + d1; lsum += (double)(d1 * d1);
        float d2 = q.z - xv.z; r.z = xv.z + d2; lsum += (double)(d2 * d2);
        float d3 = q.w - xv.w; r.w = xv.w + d3; lsum += (double)(d3 * d3);
        o4[i] = r;
    }
    sred[threadIdx.x] = lsum;
    __syncthreads();
    #pragma unroll
    for (int s = 128; s; s >>= 1) {
        if (threadIdx.x < s) sred[threadIdx.x] += sred[threadIdx.x + s];
        __syncthreads();
    }
    if (threadIdx.x == 0) g_part[blockIdx.x] = sred[0];
}

// ---------------------------------------------------------------------------
// Final loss reduction + tail fill
// ---------------------------------------------------------------------------
__global__ void loss_kernel(float* __restrict__ out, int out_size) {
    __shared__ double sred[256];
    double s = 0.0;
    for (int i = threadIdx.x; i < LOSS_BLOCKS; i += 256) s += g_part[i];
    sred[threadIdx.x] = s;
    __syncthreads();
    #pragma unroll
    for (int k = 128; k; k >>= 1) {
        if (threadIdx.x < k) sred[threadIdx.x] += sred[threadIdx.x + k];
        __syncthreads();
    }
    const int nq = NVEC * DIM;
    if (threadIdx.x == 0) {
        double m = sred[0] / (double)nq;
        float mf = (float)m;
        float loss = mf + 0.25f * mf;
        if (out_size == nq + 1)      out[nq] = loss;
        else if (out_size == 1)      out[0] = loss;
        else if (out_size > nq)      out[out_size - 1] = loss;
    }
    for (int i = nq + 1 + threadIdx.x; i < out_size - 1; i += 256) out[i] = 0.f;
}

// ---------------------------------------------------------------------------
extern "C" void kernel_launch(void* const* d_in, const int* in_sizes, int n_in,
                              void* d_out, int out_size) {
    const float* x  = (const float*)d_in[0];
    const float* cb = (const float*)d_in[1];
    if (n_in >= 2 && in_sizes[0] == KCB * DIM && in_sizes[1] == NVEC * DIM) {
        const float* t = x; x = cb; cb = t;
    }
    float* out = (float*)d_out;

    rownorm_kernel<<<NVEC / 8, 256>>>(x,  NVEC, 0);
    rownorm_kernel<<<KCB  / 8, 256>>>(cb, KCB,  1);
    vq_argmin_kernel<<<NVEC / BN, 256>>>(x, cb);
    vq_output_kernel<<<LOSS_BLOCKS, 256>>>(x, cb, out);
    loss_kernel<<<1, 256>>>(out, out_size);
}

// round 5
// speedup vs baseline: 2.7811x; 2.7784x over previous
#include <cuda_runtime.h>
#include <cstdint>

#define NVEC 65536
#define DIM  256
#define KCB  4096
#define LOSS_BLOCKS 1184
#define CAND_MAX 24
#define TH 1e-3f

__device__ float  g_x2[NVEC];
__device__ float  g_e2[KCB];
__device__ int    g_idx[NVEC];
__device__ double g_part[LOSS_BLOCKS];
__device__ float  g_bperm[KCB * DIM];   // tf32-converted, fragment-permuted codebook
__device__ int    g_fb_rows[NVEC];
__device__ int    g_fb_count;

__device__ __forceinline__ unsigned fenc(float f) {
    unsigned u = __float_as_uint(f);
    return (u & 0x80000000u) ? ~u : (u | 0x80000000u);
}
__device__ __forceinline__ float fdec(unsigned e) {
    unsigned u = (e & 0x80000000u) ? (e ^ 0x80000000u) : ~e;
    return __uint_as_float(u);
}
__device__ __forceinline__ uint32_t f2tf32(float f) {
    uint32_t r; asm("cvt.rna.tf32.f32 %0, %1;" : "=r"(r) : "f"(f)); return r;
}

// Exact fp32 distance, numerics identical to the round-1 kernel (rel_err 0.0):
// sequential fma chain over d=0..255, then t - 2*acc.
__device__ __forceinline__ float exact_dist(const float* __restrict__ xr,
                                            const float* __restrict__ cr,
                                            float x2, float e2) {
    const float4* x4 = reinterpret_cast<const float4*>(xr);
    const float4* c4 = reinterpret_cast<const float4*>(cr);
    float acc = 0.f;
    #pragma unroll 8
    for (int q = 0; q < 64; q++) {
        float4 a = x4[q], b = c4[q];
        acc = fmaf(a.x, b.x, acc);
        acc = fmaf(a.y, b.y, acc);
        acc = fmaf(a.z, b.z, acc);
        acc = fmaf(a.w, b.w, acc);
    }
    float t = x2 + e2;
    return t - 2.0f * acc;
}

// ---------------------------------------------------------------------------
// Row squared-norms (unchanged, passing). Also zeroes the fallback counter.
// ---------------------------------------------------------------------------
__global__ void rownorm_kernel(const float* __restrict__ v, int rows, int which) {
    if (which == 0 && blockIdx.x == 0 && threadIdx.x == 0) g_fb_count = 0;
    int row  = blockIdx.x * (blockDim.x >> 5) + (threadIdx.x >> 5);
    int lane = threadIdx.x & 31;
    if (row >= rows) return;
    const float4* p = reinterpret_cast<const float4*>(v + (size_t)row * DIM);
    float4 a = p[lane];
    float4 b = p[lane + 32];
    float s = ((a.x * a.x + a.y * a.y) + (a.z * a.z + a.w * a.w))
            + ((b.x * b.x + b.y * b.y) + (b.z * b.z + b.w * b.w));
    #pragma unroll
    for (int off = 16; off; off >>= 1)
        s += __shfl_xor_sync(0xffffffffu, s, off);
    if (lane == 0) {
        if (which) g_e2[row] = s;
        else       g_x2[row] = s;
    }
}

// ---------------------------------------------------------------------------
// Pre-convert + pre-permute codebook into mma.m16n8k8 B-fragment layout.
// bperm[chunk 128][ks 8][nb 16][lane 32][reg 2]
//   chunk = kt*4+dc ; code = kt*128 + nb*8 + (lane>>2)
//   d = dc*64 + ks*8 + (lane&3) + reg*4
// ---------------------------------------------------------------------------
__global__ void bperm_kernel(const float* __restrict__ cb) {
    int o = blockIdx.x * 256 + threadIdx.x;        // grid 4096 -> 1,048,576
    int reg = o & 1, lane = (o >> 1) & 31, nb = (o >> 6) & 15, ks = (o >> 10) & 7;
    int chunk = o >> 13, kt = chunk >> 2, dc = chunk & 3;
    int tig = lane & 3, gg = lane >> 2;
    int code = kt * 128 + nb * 8 + gg;
    int d = dc * 64 + ks * 8 + tig + reg * 4;
    g_bperm[o] = __uint_as_float(f2tf32(cb[(size_t)code * DIM + d]));
}

// ---------------------------------------------------------------------------
// tf32 mma.sync distance GEMM + candidate collection + exact fp32 rescore.
// CTA: 128 rows x 4096 codes. 8 warps in 2x4; warp tile 64 rows x 32 codes.
// ---------------------------------------------------------------------------
#define MMA8(ac, av, bv) \
    asm volatile("mma.sync.aligned.m16n8k8.row.col.f32.tf32.tf32.f32 " \
        "{%0,%1,%2,%3},{%4,%5,%6,%7},{%8,%9},{%0,%1,%2,%3};" \
        : "+f"((ac)[0]), "+f"((ac)[1]), "+f"((ac)[2]), "+f"((ac)[3]) \
        : "r"((av).x), "r"((av).y), "r"((av).z), "r"((av).w), \
          "r"((bv).x), "r"((bv).y))

#define LOAD_CHUNK(c, buf) do {                                               \
    const float* _src = g_bperm + (size_t)(c) * 8192 + tid * 4;               \
    uint32_t _dst = bsb + (uint32_t)(buf) * 32768u + (uint32_t)tid * 16u;     \
    _Pragma("unroll")                                                         \
    for (int _j = 0; _j < 8; _j++)                                            \
        asm volatile("cp.async.cg.shared.global [%0], [%1], 16;"              \
                     :: "r"(_dst + _j * 4096u), "l"(_src + _j * 1024) : "memory"); \
    asm volatile("cp.async.commit_group;" ::: "memory");                      \
} while (0)

__global__ __launch_bounds__(256, 1)
void vq_mma_kernel(const float* __restrict__ x, const float* __restrict__ cb) {
    extern __shared__ float dsm[];
    float* As = dsm;               // 32768 floats = 128KB (A fragments)
    float* Bs = dsm + 32768;       // 16384 floats = 64KB  (2 x 32KB chunks)
    __shared__ float x2s[128];
    __shared__ unsigned rmin[128];
    __shared__ int scnt[128];
    __shared__ unsigned short cand[128 * CAND_MAX];
    __shared__ unsigned long long red[128];

    const int tid = threadIdx.x, lane = tid & 31, warp = tid >> 5;
    const int wr = warp >> 2, wc = warp & 3;
    const int gg = lane >> 2, tig = lane & 3;
    const int row0 = blockIdx.x * 128;

    uint32_t bsb;
    asm("{ .reg .u64 t; cvta.to.shared.u64 t, %1; cvt.u32.u64 %0, t; }"
        : "=r"(bsb) : "l"(Bs));

    LOAD_CHUNK(0, 0);   // overlap first B chunk with A prologue

    if (tid < 128) {
        x2s[tid] = g_x2[row0 + tid];
        rmin[tid] = 0xFFFFFFFFu;
        scnt[tid] = 0;
        red[tid] = ~0ull;
    }

    // ---- A prologue: convert x rows to tf32 in fragment-permuted layout ----
    // A frag (m16k8): a0=(g,tig) a1=(g+8,tig) a2=(g,tig+4) a3=(g+8,tig+4)
    #pragma unroll 4
    for (int i = 0; i < 128; i++) {
        float v = x[(size_t)(row0 + i) * DIM + tid];
        uint32_t t = f2tf32(v);
        int rb = i >> 4, ks = tid >> 3;
        int ln = ((i & 7) << 2) | (tid & 3);
        int rg = ((i >> 3) & 1) | (((tid >> 2) & 1) << 1);
        As[((rb * 32 + ks) << 7) + (ln << 2) + rg] = __uint_as_float(t);
    }
    __syncthreads();

    float acc[4][4][4];

    for (int kt = 0; kt < 32; kt++) {
        #pragma unroll
        for (int rb = 0; rb < 4; rb++)
            #pragma unroll
            for (int nb = 0; nb < 4; nb++)
                #pragma unroll
                for (int cc = 0; cc < 4; cc++) acc[rb][nb][cc] = 0.f;

        for (int dc = 0; dc < 4; dc++) {
            int ic = kt * 4 + dc;
            if (ic + 1 < 128) {
                LOAD_CHUNK(ic + 1, (ic + 1) & 1);
                asm volatile("cp.async.wait_group 1;" ::: "memory");
            } else {
                asm volatile("cp.async.wait_group 0;" ::: "memory");
            }
            __syncthreads();
            const float* B = Bs + (ic & 1) * 8192;

            #pragma unroll
            for (int ks = 0; ks < 8; ks++) {
                int ksg = dc * 8 + ks;
                uint4 A4[4];
                uint2 B2[4];
                #pragma unroll
                for (int rb = 0; rb < 4; rb++)
                    A4[rb] = *reinterpret_cast<const uint4*>(
                        As + (((wr * 4 + rb) * 32 + ksg) << 7) + (lane << 2));
                #pragma unroll
                for (int nb = 0; nb < 4; nb++)
                    B2[nb] = *reinterpret_cast<const uint2*>(
                        B + ((ks * 16 + wc * 4 + nb) * 32 + lane) * 2);
                #pragma unroll
                for (int rb = 0; rb < 4; rb++)
                    #pragma unroll
                    for (int nb = 0; nb < 4; nb++)
                        MMA8(acc[rb][nb], A4[rb], B2[nb]);
            }
            __syncthreads();
        }

        // ---- epilogue: approx dist, running min, candidate collection ----
        float e2v[4][2];
        #pragma unroll
        for (int nb = 0; nb < 4; nb++) {
            int c0 = kt * 128 + wc * 32 + nb * 8 + tig * 2;
            e2v[nb][0] = g_e2[c0];
            e2v[nb][1] = g_e2[c0 + 1];
        }
        #pragma unroll
        for (int rb = 0; rb < 4; rb++)
            #pragma unroll
            for (int nb = 0; nb < 4; nb++)
                #pragma unroll
                for (int cc = 0; cc < 4; cc++) {
                    int h = cc >> 1, w = cc & 1;
                    int r = wr * 64 + rb * 16 + gg + h * 8;
                    float dist = (x2s[r] + e2v[nb][w]) - 2.0f * acc[rb][nb][cc];
                    acc[rb][nb][cc] = dist;
                    atomicMin(&rmin[r], fenc(dist));
                }
        __syncthreads();
        #pragma unroll
        for (int rb = 0; rb < 4; rb++)
            #pragma unroll
            for (int nb = 0; nb < 4; nb++)
                #pragma unroll
                for (int cc = 0; cc < 4; cc++) {
                    int h = cc >> 1, w = cc & 1;
                    int r = wr * 64 + rb * 16 + gg + h * 8;
                    float thr = fdec(rmin[r]) + TH;
                    if (acc[rb][nb][cc] < thr) {
                        int s = atomicAdd(&scnt[r], 1);
                        if (s < CAND_MAX) {
                            int code = kt * 128 + wc * 32 + nb * 8 + tig * 2 + w;
                            cand[r * CAND_MAX + s] = (unsigned short)code;
                        }
                    }
                }
        // next rmin writes are separated by >=1 __syncthreads in the dc loop
    }

    // ---- exact fp32 rescore of candidates ----
    __syncthreads();
    for (int t2 = 0; t2 < 16; t2++) {
        int r = warp * 16 + t2;
        int c = scnt[r];
        if (c > CAND_MAX) {
            if (lane == 0) {
                int fi = atomicAdd(&g_fb_count, 1);
                g_fb_rows[fi] = row0 + r;
            }
            continue;
        }
        if (lane < c) {
            int idx = cand[r * CAND_MAX + lane];
            float dist = exact_dist(x + (size_t)(row0 + r) * DIM,
                                    cb + (size_t)idx * DIM, x2s[r], g_e2[idx]);
            unsigned long long key =
                ((unsigned long long)fenc(dist) << 32) | (unsigned)idx;
            atomicMin(&red[r], key);
        }
    }
    __syncthreads();
    if (tid < 128 && scnt[tid] <= CAND_MAX)
        g_idx[row0 + tid] = (int)(red[tid] & 0xFFFFFFFFu);
}

// ---------------------------------------------------------------------------
// Fallback: exact full scan for rows whose candidate buffer overflowed.
// ---------------------------------------------------------------------------
__global__ void fb_kernel(const float* __restrict__ x, const float* __restrict__ cb) {
    __shared__ unsigned long long rr;
    int n = g_fb_count;
    for (int fi = blockIdx.x; fi < n; fi += gridDim.x) {
        int row = g_fb_rows[fi];
        if (threadIdx.x == 0) rr = ~0ull;
        __syncthreads();
        float x2 = g_x2[row];
        for (int c = threadIdx.x; c < KCB; c += blockDim.x) {
            float dist = exact_dist(x + (size_t)row * DIM, cb + (size_t)c * DIM,
                                    x2, g_e2[c]);
            unsigned long long key =
                ((unsigned long long)fenc(dist) << 32) | (unsigned)c;
            atomicMin(&rr, key);
        }
        __syncthreads();
        if (threadIdx.x == 0) g_idx[row] = (int)(rr & 0xFFFFFFFFu);
        __syncthreads();
    }
}

// ---------------------------------------------------------------------------
// Gather + straight-through output + loss (unchanged, passing)
// ---------------------------------------------------------------------------
__global__ void vq_output_kernel(const float* __restrict__ x,
                                 const float* __restrict__ cb,
                                 float* __restrict__ out) {
    __shared__ double sred[256];
    double lsum = 0.0;
    const int nthreads = gridDim.x * blockDim.x;
    const int total4 = NVEC * DIM / 4;
    const float4* x4 = reinterpret_cast<const float4*>(x);
    float4* o4 = reinterpret_cast<float4*>(out);

    for (int i = blockIdx.x * blockDim.x + threadIdx.x; i < total4; i += nthreads) {
        int n = i >> 6;
        int idx = g_idx[n];
        float4 q  = reinterpret_cast<const float4*>(cb + (size_t)idx * DIM)[i & 63];
        float4 xv = x4[i];
        float4 r;
        float d0 = q.x - xv.x; r.x = xv.x + d0; lsum += (double)(d0 * d0);
        float d1 = q.y - xv.y; r.y = xv.y + d1; lsum += (double)(d1 * d1);
        float d2 = q.z - xv.z; r.z = xv.z + d2; lsum += (double)(d2 * d2);
        float d3 = q.w - xv.w; r.w = xv.w + d3; lsum += (double)(d3 * d3);
        o4[i] = r;
    }
    sred[threadIdx.x] = lsum;
    __syncthreads();
    #pragma unroll
    for (int s = 128; s; s >>= 1) {
        if (threadIdx.x < s) sred[threadIdx.x] += sred[threadIdx.x + s];
        __syncthreads();
    }
    if (threadIdx.x == 0) g_part[blockIdx.x] = sred[0];
}

__global__ void loss_kernel(float* __restrict__ out, int out_size) {
    __shared__ double sred[256];
    double s = 0.0;
    for (int i = threadIdx.x; i < LOSS_BLOCKS; i += 256) s += g_part[i];
    sred[threadIdx.x] = s;
    __syncthreads();
    #pragma unroll
    for (int k = 128; k; k >>= 1) {
        if (threadIdx.x < k) sred[threadIdx.x] += sred[threadIdx.x + k];
        __syncthreads();
    }
    const int nq = NVEC * DIM;
    if (threadIdx.x == 0) {
        double m = sred[0] / (double)nq;
        float mf = (float)m;
        float loss = mf + 0.25f * mf;
        if (out_size == nq + 1)      out[nq] = loss;
        else if (out_size == 1)      out[0] = loss;
        else if (out_size > nq)      out[out_size - 1] = loss;
    }
    for (int i = nq + 1 + threadIdx.x; i < out_size - 1; i += 256) out[i] = 0.f;
}

// ---------------------------------------------------------------------------
extern "C" void kernel_launch(void* const* d_in, const int* in_sizes, int n_in,
                              void* d_out, int out_size) {
    const float* x  = (const float*)d_in[0];
    const float* cb = (const float*)d_in[1];
    if (n_in >= 2 && in_sizes[0] == KCB * DIM && in_sizes[1] == NVEC * DIM) {
        const float* t = x; x = cb; cb = t;
    }
    float* out = (float*)d_out;

    cudaFuncSetAttribute(vq_mma_kernel,
                         cudaFuncAttributeMaxDynamicSharedMemorySize, 196608);

    bperm_kernel<<<KCB * DIM / 256, 256>>>(cb);
    rownorm_kernel<<<NVEC / 8, 256>>>(x,  NVEC, 0);
    rownorm_kernel<<<KCB  / 8, 256>>>(cb, KCB,  1);
    vq_mma_kernel<<<NVEC / 128, 256, 196608>>>(x, cb);
    fb_kernel<<<64, 256>>>(x, cb);
    vq_output_kernel<<<LOSS_BLOCKS, 256>>>(x, cb, out);
    loss_kernel<<<1, 256>>>(out, out_size);
}

// round 6
// speedup vs baseline: 4.0437x; 1.4540x over previous
#include <cuda_runtime.h>
#include <cstdint>

#define NVEC 65536
#define DIM  256
#define KCB  4096
#define LOSS_BLOCKS 1184
#define CAND_MAX 32
#define TH 1.5e-3f

__device__ float    g_x2[NVEC];
__device__ float    g_e2[KCB];
__device__ int      g_idx[NVEC];
__device__ double   g_part[LOSS_BLOCKS];
__device__ uint32_t g_bperm[KCB * DIM / 2];   // bf16x2 fragment-permuted codebook
__device__ int      g_fb_rows[NVEC];
__device__ int      g_fb_count;

__device__ __forceinline__ unsigned fenc(float f) {
    unsigned u = __float_as_uint(f);
    return (u & 0x80000000u) ? ~u : (u | 0x80000000u);
}
__device__ __forceinline__ float fdec(unsigned e) {
    unsigned u = (e & 0x80000000u) ? (e ^ 0x80000000u) : ~e;
    return __uint_as_float(u);
}
// pack bf16x2: lo half = v0, hi half = v1
__device__ __forceinline__ uint32_t bfpack(float v0, float v1) {
    uint32_t r;
    asm("cvt.rn.bf16x2.f32 %0, %1, %2;" : "=r"(r) : "f"(v1), "f"(v0));
    return r;
}

// Exact fp32 distance — identical recipe to round-1 (rel_err 0.0): serial fma
// chain over d, then (x2+e2) - 2*acc.
__device__ __forceinline__ float exact_dist(const float* __restrict__ xr,
                                            const float* __restrict__ cr,
                                            float x2, float e2) {
    const float4* x4 = reinterpret_cast<const float4*>(xr);
    const float4* c4 = reinterpret_cast<const float4*>(cr);
    float acc = 0.f;
    #pragma unroll 8
    for (int q = 0; q < 64; q++) {
        float4 a = x4[q], b = c4[q];
        acc = fmaf(a.x, b.x, acc);
        acc = fmaf(a.y, b.y, acc);
        acc = fmaf(a.z, b.z, acc);
        acc = fmaf(a.w, b.w, acc);
    }
    float t = x2 + e2;
    return t - 2.0f * acc;
}

// ---------------------------------------------------------------------------
__global__ void rownorm_kernel(const float* __restrict__ v, int rows, int which) {
    if (which == 0 && blockIdx.x == 0 && threadIdx.x == 0) g_fb_count = 0;
    int row  = blockIdx.x * (blockDim.x >> 5) + (threadIdx.x >> 5);
    int lane = threadIdx.x & 31;
    if (row >= rows) return;
    const float4* p = reinterpret_cast<const float4*>(v + (size_t)row * DIM);
    float4 a = p[lane];
    float4 b = p[lane + 32];
    float s = ((a.x * a.x + a.y * a.y) + (a.z * a.z + a.w * a.w))
            + ((b.x * b.x + b.y * b.y) + (b.z * b.z + b.w * b.w));
    #pragma unroll
    for (int off = 16; off; off >>= 1)
        s += __shfl_xor_sync(0xffffffffu, s, off);
    if (lane == 0) {
        if (which) g_e2[row] = s;
        else       g_x2[row] = s;
    }
}

// ---------------------------------------------------------------------------
// Pre-convert codebook to bf16 in mma.m16n8k16 B-fragment layout.
// Layout: [chunk 128][kb 4][nb 16][lane 32][reg 2] (u32 = bf16x2)
//   chunk = kt*4 + dc covers codes kt*128.. and d = dc*64..dc*64+63
//   code = kt*128 + nb*8 + (lane>>2)
//   d0   = dc*64 + kb*16 + 2*(lane&3) + reg*8   (pair d0, d0+1)
// ---------------------------------------------------------------------------
__global__ void bperm_kernel(const float* __restrict__ cb) {
    int o = blockIdx.x * 256 + threadIdx.x;    // total 524288
    int reg = o & 1, lane = (o >> 1) & 31, nb = (o >> 6) & 15, kb = (o >> 10) & 3;
    int chunk = o >> 12, kt = chunk >> 2, dc = chunk & 3;
    int gg = lane >> 2, tig = lane & 3;
    int code = kt * 128 + nb * 8 + gg;
    int d0 = dc * 64 + kb * 16 + 2 * tig + reg * 8;
    const float* r = cb + (size_t)code * DIM;
    g_bperm[o] = bfpack(r[d0], r[d0 + 1]);
}

// ---------------------------------------------------------------------------
// bf16 mma.sync distance GEMM + candidate collection + exact fp32 rescore.
// CTA: 128 rows x 4096 codes. 8 warps (2 wr x 4 wc); warp tile 64x32.
// ---------------------------------------------------------------------------
#define MMA16(ac, av, bv) \
    asm volatile("mma.sync.aligned.m16n8k16.row.col.f32.bf16.bf16.f32 " \
        "{%0,%1,%2,%3},{%4,%5,%6,%7},{%8,%9},{%0,%1,%2,%3};" \
        : "+f"((ac)[0]), "+f"((ac)[1]), "+f"((ac)[2]), "+f"((ac)[3]) \
        : "r"((av).x), "r"((av).y), "r"((av).z), "r"((av).w), \
          "r"((bv).x), "r"((bv).y))

// chunk = 16KB: 256 threads x 16B x 4
#define LOAD_CHUNK(c, buf) do {                                               \
    const uint32_t* _src = g_bperm + (size_t)(c) * 4096 + tid * 4;            \
    uint32_t _dst = bsb + (uint32_t)(buf) * 16384u + (uint32_t)tid * 16u;     \
    _Pragma("unroll")                                                         \
    for (int _j = 0; _j < 4; _j++)                                            \
        asm volatile("cp.async.cg.shared.global [%0], [%1], 16;"              \
                     :: "r"(_dst + _j * 4096u), "l"(_src + _j * 1024) : "memory"); \
    asm volatile("cp.async.commit_group;" ::: "memory");                      \
} while (0)

__global__ __launch_bounds__(256, 2)
void vq_mma_kernel(const float* __restrict__ x, const float* __restrict__ cb) {
    extern __shared__ uint32_t dsm[];
    uint32_t* As = dsm;            // 16384 u32 = 64KB  (A bf16 fragments)
    uint32_t* Bs = dsm + 16384;    //  8192 u32 = 32KB  (2 x 16KB B chunks)
    __shared__ float x2s[128];
    __shared__ unsigned rmin[128];
    __shared__ int scnt[128];
    __shared__ unsigned short cand[128 * CAND_MAX];
    __shared__ unsigned long long red[128];

    const int tid = threadIdx.x, lane = tid & 31, warp = tid >> 5;
    const int wr = warp >> 2, wc = warp & 3;
    const int gg = lane >> 2, tig = lane & 3;
    const int row0 = blockIdx.x * 128;

    uint32_t bsb;
    asm("{ .reg .u64 t; cvta.to.shared.u64 t, %1; cvt.u32.u64 %0, t; }"
        : "=r"(bsb) : "l"(Bs));

    LOAD_CHUNK(0, 0);

    if (tid < 128) {
        x2s[tid] = g_x2[row0 + tid];
        rmin[tid] = 0xFFFFFFFFu;
        scnt[tid] = 0;
        red[tid] = ~0ull;
    }

    // ---- A prologue: x rows -> bf16 fragment layout in smem ----
    // thread handles (row = 2i + tid>>7, d-pair d0 = (tid&127)*2)
    {
        const int d0 = (tid & 127) << 1;
        const int rsel = tid >> 7;
        const int kbg = d0 >> 4;
        const int ln  = (d0 & 7) >> 1;            // tig part of lane
        const int kh  = (d0 >> 3) & 1;
        #pragma unroll 4
        for (int i = 0; i < 64; i++) {
            int row = (i << 1) | rsel;
            float2 v = *reinterpret_cast<const float2*>(
                x + (size_t)(row0 + row) * DIM + d0);
            uint32_t p = bfpack(v.x, v.y);
            int mb = row >> 4;
            int lfull = ((row & 7) << 2) | ln;
            int reg = ((row >> 3) & 1) | (kh << 1);
            As[((mb * 16 + kbg) << 7) + (lfull << 2) + reg] = p;
        }
    }
    __syncthreads();

    float acc[4][4][4];

    for (int kt = 0; kt < 32; kt++) {
        #pragma unroll
        for (int rb = 0; rb < 4; rb++)
            #pragma unroll
            for (int nb = 0; nb < 4; nb++)
                #pragma unroll
                for (int cc = 0; cc < 4; cc++) acc[rb][nb][cc] = 0.f;

        for (int dc = 0; dc < 4; dc++) {
            int ic = kt * 4 + dc;
            if (ic + 1 < 128) {
                LOAD_CHUNK(ic + 1, (ic + 1) & 1);
                asm volatile("cp.async.wait_group 1;" ::: "memory");
            } else {
                asm volatile("cp.async.wait_group 0;" ::: "memory");
            }
            __syncthreads();
            const uint32_t* B = Bs + (ic & 1) * 4096;

            #pragma unroll
            for (int kb = 0; kb < 4; kb++) {
                int kbg = dc * 4 + kb;
                uint4 A4[4];
                uint2 B2[4];
                #pragma unroll
                for (int rb = 0; rb < 4; rb++)
                    A4[rb] = *reinterpret_cast<const uint4*>(
                        As + (((wr * 4 + rb) * 16 + kbg) << 7) + (lane << 2));
                #pragma unroll
                for (int nb = 0; nb < 4; nb++)
                    B2[nb] = *reinterpret_cast<const uint2*>(
                        B + ((kb * 16 + wc * 4 + nb) * 32 + lane) * 2);
                #pragma unroll
                for (int rb = 0; rb < 4; rb++)
                    #pragma unroll
                    for (int nb = 0; nb < 4; nb++)
                        MMA16(acc[rb][nb], A4[rb], B2[nb]);
            }
            __syncthreads();
        }

        // ---- epilogue: dist, shfl-reduced row-min, candidate collection ----
        float e2v[4][2];
        #pragma unroll
        for (int nb = 0; nb < 4; nb++) {
            int c0 = kt * 128 + wc * 32 + nb * 8 + tig * 2;
            e2v[nb][0] = g_e2[c0];
            e2v[nb][1] = g_e2[c0 + 1];
        }
        #pragma unroll
        for (int rb = 0; rb < 4; rb++) {
            #pragma unroll
            for (int h = 0; h < 2; h++) {
                int r = wr * 64 + rb * 16 + gg + h * 8;
                float m = 3.4e38f;
                #pragma unroll
                for (int nb = 0; nb < 4; nb++)
                    #pragma unroll
                    for (int w = 0; w < 2; w++) {
                        int cc = h * 2 + w;
                        float dist = (x2s[r] + e2v[nb][w]) - 2.0f * acc[rb][nb][cc];
                        acc[rb][nb][cc] = dist;
                        m = fminf(m, dist);
                    }
                m = fminf(m, __shfl_xor_sync(0xffffffffu, m, 1));
                m = fminf(m, __shfl_xor_sync(0xffffffffu, m, 2));
                if (tig == 0) atomicMin(&rmin[r], fenc(m));
            }
        }
        __syncthreads();
        #pragma unroll
        for (int rb = 0; rb < 4; rb++)
            #pragma unroll
            for (int h = 0; h < 2; h++) {
                int r = wr * 64 + rb * 16 + gg + h * 8;
                float thr = fdec(rmin[r]) + TH;
                #pragma unroll
                for (int nb = 0; nb < 4; nb++)
                    #pragma unroll
                    for (int w = 0; w < 2; w++) {
                        if (acc[rb][nb][h * 2 + w] < thr) {
                            int s = atomicAdd(&scnt[r], 1);
                            if (s < CAND_MAX) {
                                int code = kt * 128 + wc * 32 + nb * 8 + tig * 2 + w;
                                cand[r * CAND_MAX + s] = (unsigned short)code;
                            }
                        }
                    }
            }
    }

    // ---- exact fp32 rescore ----
    __syncthreads();
    for (int t2 = 0; t2 < 16; t2++) {
        int r = warp * 16 + t2;
        int c = scnt[r];
        if (c > CAND_MAX) {
            if (lane == 0) {
                int fi = atomicAdd(&g_fb_count, 1);
                g_fb_rows[fi] = row0 + r;
            }
            continue;
        }
        if (lane < c) {
            int idx = cand[r * CAND_MAX + lane];
            float dist = exact_dist(x + (size_t)(row0 + r) * DIM,
                                    cb + (size_t)idx * DIM, x2s[r], g_e2[idx]);
            unsigned long long key =
                ((unsigned long long)fenc(dist) << 32) | (unsigned)idx;
            atomicMin(&red[r], key);
        }
    }
    __syncthreads();
    if (tid < 128 && scnt[tid] <= CAND_MAX)
        g_idx[row0 + tid] = (int)(red[tid] & 0xFFFFFFFFu);
}

// ---------------------------------------------------------------------------
// Fallback: exact full scan for overflowed rows.
// ---------------------------------------------------------------------------
__global__ void fb_kernel(const float* __restrict__ x, const float* __restrict__ cb) {
    __shared__ unsigned long long rr;
    int n = g_fb_count;
    for (int fi = blockIdx.x; fi < n; fi += gridDim.x) {
        int row = g_fb_rows[fi];
        if (threadIdx.x == 0) rr = ~0ull;
        __syncthreads();
        float x2 = g_x2[row];
        for (int c = threadIdx.x; c < KCB; c += blockDim.x) {
            float dist = exact_dist(x + (size_t)row * DIM, cb + (size_t)c * DIM,
                                    x2, g_e2[c]);
            unsigned long long key =
                ((unsigned long long)fenc(dist) << 32) | (unsigned)c;
            atomicMin(&rr, key);
        }
        __syncthreads();
        if (threadIdx.x == 0) g_idx[row] = (int)(rr & 0xFFFFFFFFu);
        __syncthreads();
    }
}

// ---------------------------------------------------------------------------
__global__ void vq_output_kernel(const float* __restrict__ x,
                                 const float* __restrict__ cb,
                                 float* __restrict__ out) {
    __shared__ double sred[256];
    double lsum = 0.0;
    const int nthreads = gridDim.x * blockDim.x;
    const int total4 = NVEC * DIM / 4;
    const float4* x4 = reinterpret_cast<const float4*>(x);
    float4* o4 = reinterpret_cast<float4*>(out);

    for (int i = blockIdx.x * blockDim.x + threadIdx.x; i < total4; i += nthreads) {
        int n = i >> 6;
        int idx = g_idx[n];
        float4 q  = reinterpret_cast<const float4*>(cb + (size_t)idx * DIM)[i & 63];
        float4 xv = x4[i];
        float4 r;
        float d0 = q.x - xv.x; r.x = xv.x + d0; lsum += (double)(d0 * d0);
        float d1 = q.y - xv.y; r.y = xv.y + d1; lsum += (double)(d1 * d1);
        float d2 = q.z - xv.z; r.z = xv.z + d2; lsum += (double)(d2 * d2);
        float d3 = q.w - xv.w; r.w = xv.w + d3; lsum += (double)(d3 * d3);
        o4[i] = r;
    }
    sred[threadIdx.x] = lsum;
    __syncthreads();
    #pragma unroll
    for (int s = 128; s; s >>= 1) {
        if (threadIdx.x < s) sred[threadIdx.x] += sred[threadIdx.x + s];
        __syncthreads();
    }
    if (threadIdx.x == 0) g_part[blockIdx.x] = sred[0];
}

__global__ void loss_kernel(float* __restrict__ out, int out_size) {
    __shared__ double sred[256];
    double s = 0.0;
    for (int i = threadIdx.x; i < LOSS_BLOCKS; i += 256) s += g_part[i];
    sred[threadIdx.x] = s;
    __syncthreads();
    #pragma unroll
    for (int k = 128; k; k >>= 1) {
        if (threadIdx.x < k) sred[threadIdx.x] += sred[threadIdx.x + k];
        __syncthreads();
    }
    const int nq = NVEC * DIM;
    if (threadIdx.x == 0) {
        double m = sred[0] / (double)nq;
        float mf = (float)m;
        float loss = mf + 0.25f * mf;
        if (out_size == nq + 1)      out[nq] = loss;
        else if (out_size == 1)      out[0] = loss;
        else if (out_size > nq)      out[out_size - 1] = loss;
    }
    for (int i = nq + 1 + threadIdx.x; i < out_size - 1; i += 256) out[i] = 0.f;
}

// ---------------------------------------------------------------------------
extern "C" void kernel_launch(void* const* d_in, const int* in_sizes, int n_in,
                              void* d_out, int out_size) {
    const float* x  = (const float*)d_in[0];
    const float* cb = (const float*)d_in[1];
    if (n_in >= 2 && in_sizes[0] == KCB * DIM && in_sizes[1] == NVEC * DIM) {
        const float* t = x; x = cb; cb = t;
    }
    float* out = (float*)d_out;

    cudaFuncSetAttribute(vq_mma_kernel,
                         cudaFuncAttributeMaxDynamicSharedMemorySize, 98304);

    bperm_kernel<<<KCB * DIM / 2 / 256, 256>>>(cb);
    rownorm_kernel<<<NVEC / 8, 256>>>(x,  NVEC, 0);
    rownorm_kernel<<<KCB  / 8, 256>>>(cb, KCB,  1);
    vq_mma_kernel<<<NVEC / 128, 256, 98304>>>(x, cb);
    fb_kernel<<<64, 256>>>(x, cb);
    vq_output_kernel<<<LOSS_BLOCKS, 256>>>(x, cb, out);
    loss_kernel<<<1, 256>>>(out, out_size);
}